// round 11
// baseline (speedup 1.0000x reference)
#include <cuda_runtime.h>
#include <math.h>
#include <stdint.h>

// Problem dims
#define NB 64
#define NS 256
#define NH 1024
#define NE 512
#define NV 10000
#define NT 64
#define ND 512
#define NG 2048     // 4*D
#define NXK 1536    // E+H

// Output layout: decoder_outputs, h, c, attentions
#define OUT_LOG 0
#define OUT_H   (NB*NT*NV)
#define OUT_C   (OUT_H + 2*NB*ND)
#define OUT_ATTN (OUT_C + 2*NB*ND)

#define NSP 8      // split-K ways for qwa / lstm

// ---------------------------------------------------------------------------
// Scratch (device globals)
__device__ float g_Uk[NB*NS*NH];            // 64 MB
__device__ float g_qWa_part[NSP][NB*NH];
__device__ float g_scores[NB*NS];
__device__ float g_x[NB*NXK];               // [emb | ctx], tf32-rounded
__device__ float g_hcat[NB*NH];             // exact h, [b][dir*512+j]
__device__ float g_hcat32[NB*NH];           // tf32-rounded h
__device__ float g_c[2*NB*ND];
__device__ float g_gates_part[NSP][2][NB*NG];
// tf32-rounded weights / enc
__device__ float g_r_outW[NV*NH];
__device__ float g_r_Wa[NH*NH];
__device__ float g_r_Ua[NH*NH];
__device__ float g_r_Wih[2][NG*NXK];
__device__ float g_r_Whh[2][NG*ND];
__device__ float g_enc32[NB*NS*NH];

// ---------------------------------------------------------------------------
__device__ __forceinline__ float tanh_fast(float x) {
    float y;
    asm("tanh.approx.f32 %0, %1;" : "=f"(y) : "f"(x));
    return y;
}
__device__ __forceinline__ float sigmoid_acc(float x) {
    return 1.0f / (1.0f + __expf(-x));
}
__device__ __forceinline__ float rna_tf32(float x) {
    uint32_t u;
    asm("cvt.rna.tf32.f32 %0, %1;" : "=r"(u) : "f"(x));
    return __uint_as_float(u);
}
__device__ __forceinline__ void cp16(void* s, const void* g) {
    uint32_t sa = (uint32_t)__cvta_generic_to_shared(s);
    asm volatile("cp.async.cg.shared.global [%0], [%1], 16;\n" :: "r"(sa), "l"(g));
}
__device__ __forceinline__ void cp_commit() {
    asm volatile("cp.async.commit_group;\n");
}
__device__ __forceinline__ void cp_wait3() {
    asm volatile("cp.async.wait_group 3;\n");
}
__device__ __forceinline__ void mma_tf32(float (&d)[4], uint32_t a0, uint32_t a1,
                                         uint32_t a2, uint32_t a3,
                                         uint32_t b0, uint32_t b1) {
    asm volatile(
        "mma.sync.aligned.m16n8k8.row.col.f32.tf32.tf32.f32 "
        "{%0,%1,%2,%3}, {%4,%5,%6,%7}, {%8,%9}, {%0,%1,%2,%3};\n"
        : "+f"(d[0]), "+f"(d[1]), "+f"(d[2]), "+f"(d[3])
        : "r"(a0), "r"(a1), "r"(a2), "r"(a3), "r"(b0), "r"(b1));
}

// ---------------------------------------------------------------------------
// Fused tf32 pre-rounding of all weights + enc
#define RN_OUTW (NV*NH)
#define RN_WA   (NH*NH)
#define RN_UA   (NH*NH)
#define RN_WIH  (NG*NXK)
#define RN_WHH  (NG*ND)
#define RN_ENC  (NB*NS*NH)
#define RN_TOT  (RN_OUTW + RN_WA + RN_UA + 2*RN_WIH + 2*RN_WHH + RN_ENC)

__global__ __launch_bounds__(256) void k_round_all(
    const float* __restrict__ outW, const float* __restrict__ Wa,
    const float* __restrict__ Ua,
    const float* __restrict__ Wihf, const float* __restrict__ Wihb,
    const float* __restrict__ Whhf, const float* __restrict__ Whhb,
    const float* __restrict__ enc) {
    long long i = (long long)blockIdx.x * 256 + threadIdx.x;
    if (i >= RN_TOT) return;
    const float* src; float* dst; long long off = i;
    if (off < RN_OUTW) { src = outW; dst = g_r_outW; }
    else if ((off -= RN_OUTW) < RN_WA) { src = Wa; dst = g_r_Wa; }
    else if ((off -= RN_WA) < RN_UA) { src = Ua; dst = g_r_Ua; }
    else if ((off -= RN_UA) < RN_WIH) { src = Wihf; dst = g_r_Wih[0]; }
    else if ((off -= RN_WIH) < RN_WIH) { src = Wihb; dst = g_r_Wih[1]; }
    else if ((off -= RN_WIH) < RN_WHH) { src = Whhf; dst = g_r_Whh[0]; }
    else if ((off -= RN_WHH) < RN_WHH) { src = Whhb; dst = g_r_Whh[1]; }
    else { off -= RN_WHH; src = enc; dst = g_enc32; }
    dst[off] = rna_tf32(src[off]);
}

// ---------------------------------------------------------------------------
__global__ __launch_bounds__(256) void k_init(const float* __restrict__ h0,
                                              const float* __restrict__ c0) {
    int idx = blockIdx.x * 256 + threadIdx.x;   // [2][64][512]
    int d = idx >> 15, b = (idx >> 9) & 63, j = idx & 511;
    g_c[idx] = c0[idx];
    float h = h0[idx];
    g_hcat[b * NH + d * 512 + j] = h;
    g_hcat32[b * NH + d * 512 + j] = rna_tf32(h);
}

// ---------------------------------------------------------------------------
// tf32 MMA core: 64 W-rows x 64 act-cols per block (4 warps x 16 rows, NBM=8).
// K-chunk 16, 4 smem buffers, cp.async pipeline depth 3 (wait_group 3).
// Requires threads 0..127 (threads >=128, if any, must have exited).
#define CHW 20   // padded chunk row stride (conflict-free: (20g+c)%32 distinct)
__device__ __forceinline__ void mma8_core(
    const float* __restrict__ W, int ldw,
    const float* __restrict__ Act, int lda, int b0,
    int K,
    float* __restrict__ C, long long c_stride,
    const float* __restrict__ bias,
    int n0, int Nrows)
{
    __shared__ float Wb[4][64][CHW];
    __shared__ float Ab[4][64][CHW];
    const int tid = threadIdx.x;
    const int lane = tid & 31, warp = tid >> 5;
    const int g = lane >> 2, c = lane & 3;
    const bool active = (n0 + warp * 16 + 16) <= Nrows;

    float acc[8][4];
#pragma unroll
    for (int j = 0; j < 8; j++)
#pragma unroll
        for (int i = 0; i < 4; i++) acc[j][i] = 0.f;

    const int NC = K >> 4;     // chunks of 16

    auto stage = [&](int kc) {
        int buf = kc & 3;
        int k0 = kc << 4;
#pragma unroll
        for (int i = 0; i < 2; i++) {
            int idx = i * 128 + tid;
            int r = idx >> 2, seg = idx & 3;
            int row = n0 + r; if (row >= Nrows) row = Nrows - 1;
            cp16(&Wb[buf][r][seg * 4], W + (size_t)row * ldw + k0 + seg * 4);
        }
#pragma unroll
        for (int i = 0; i < 2; i++) {
            int idx = i * 128 + tid;
            int b = idx >> 2, seg = idx & 3;
            cp16(&Ab[buf][b][seg * 4],
                 Act + (size_t)(b0 + b) * lda + k0 + seg * 4);
        }
    };

    stage(0); cp_commit();
    stage(1); cp_commit();
    stage(2); cp_commit();

    for (int kc = 0; kc < NC; kc++) {
        if (kc + 3 < NC) stage(kc + 3);
        cp_commit();
        cp_wait3();
        __syncthreads();
        if (active) {
            int buf = kc & 3;
            const int r0 = warp * 16 + g, r1 = r0 + 8;
#pragma unroll
            for (int ks = 0; ks < 2; ks++) {
                int kb = ks * 8;
                uint32_t a0 = __float_as_uint(Wb[buf][r0][kb + c]);
                uint32_t a1 = __float_as_uint(Wb[buf][r1][kb + c]);
                uint32_t a2 = __float_as_uint(Wb[buf][r0][kb + c + 4]);
                uint32_t a3 = __float_as_uint(Wb[buf][r1][kb + c + 4]);
#pragma unroll
                for (int j = 0; j < 8; j++) {
                    uint32_t b0r = __float_as_uint(Ab[buf][g + 8 * j][kb + c]);
                    uint32_t b1r = __float_as_uint(Ab[buf][g + 8 * j][kb + c + 4]);
                    mma_tf32(acc[j], a0, a1, a2, a3, b0r, b1r);
                }
            }
        }
        __syncthreads();
    }

    if (active) {
        int ng0 = n0 + warp * 16 + g, ng1 = ng0 + 8;
        float bv0 = 0.f, bv1 = 0.f;
        if (bias) { bv0 = bias[ng0]; bv1 = bias[ng1]; }
#pragma unroll
        for (int j = 0; j < 8; j++) {
            long long col = b0 + c * 2 + 8 * j;
            C[col * c_stride + ng0]       = acc[j][0] + bv0;
            C[(col + 1) * c_stride + ng0] = acc[j][1] + bv0;
            C[col * c_stride + ng1]       = acc[j][2] + bv1;
            C[(col + 1) * c_stride + ng1] = acc[j][3] + bv1;
        }
    }
}

// ---------------------------------------------------------------------------
// qwa split-K block helper: qid in [0,128); 8 splits of K=128
__device__ __forceinline__ void qwa_block(int qid) {
    int n0 = (qid & 15) * 64;
    int ks = qid >> 4;                       // 0..7
    mma8_core(g_r_Wa + ks * 128, NH,
              g_hcat32 + ks * 128, NH, 0,
              128,
              g_qWa_part[ks], NH, nullptr,
              n0, NH);
}

// Uk = enc32 @ Ua^T : grid (16, 1, 256)
__global__ __launch_bounds__(128) void k_mma_uk() {
    mma8_core(g_r_Ua, NH, g_enc32, NH, blockIdx.z * 64,
              NH, g_Uk, NH, nullptr, blockIdx.x * 64, NH);
}

// qWa partials (per-step, main stream)
__global__ __launch_bounds__(128) void k_qwa_step() {
    qwa_block(blockIdx.x);
}

// Standalone logits (used once for t = NT-1)
__global__ __launch_bounds__(128) void k_logits(float* __restrict__ out,
                                                const float* __restrict__ outb,
                                                int t) {
    mma8_core(g_r_outW, NH, g_hcat32, NH, 0,
              NH,
              out + OUT_LOG + (long long)t * NV, (long long)NT * NV,
              outb, blockIdx.x * 64, NV);
}

// LSTM gates split-K: grid 512 = 32 n-slabs x 8 ks x 2 dir
__global__ __launch_bounds__(128) void k_mma_lstm() {
    int bid = blockIdx.x;
    int n0 = (bid & 31) * 64;
    int ks = (bid >> 5) & 7;
    int d = bid >> 8;
    const float* W; const float* Act; int ldw, lda;
    if (ks < 6) { W = g_r_Wih[d] + ks * 256; ldw = NXK;
                  Act = g_x + ks * 256;      lda = NXK; }
    else        { W = g_r_Whh[d] + (ks - 6) * 256; ldw = ND;
                  Act = g_hcat32 + d * 512 + (ks - 6) * 256; lda = NH; }
    mma8_core(W, ldw, Act, lda, 0, 256,
              g_gates_part[ks][d], NG, nullptr, n0, NG);
}

// ---------------------------------------------------------------------------
// Fused scores(t) + logits(t-1) in one launch (no streams needed):
// blocks [0,2048): scores; blocks [2048,2205): logits tiles (skip when t==0).
// logits(t-1) reads g_hcat32 = h(t-1), still live until k_cell(t).
__global__ __launch_bounds__(256) void k_sclog(const float* __restrict__ Va,
                                               float* __restrict__ out,
                                               const float* __restrict__ outb,
                                               int t) {
    int bid = blockIdx.x;
    int tid = threadIdx.x;
    if (bid >= 2048) {
        // ---- logits(t-1) ----
        if (t == 0) return;
        if (tid >= 128) return;          // exited threads don't join barriers
        mma8_core(g_r_outW, NH, g_hcat32, NH, 0,
                  NH,
                  out + OUT_LOG + (long long)(t - 1) * NV, (long long)NT * NV,
                  outb, (bid - 2048) * 64, NV);
        return;
    }
    // ---- scores(t) ----
    int b = bid >> 5;
    int s0 = (bid & 31) * 8;
    __shared__ float4 qs[256];               // qWa[b][:] summed over partials
    {
        float4 r = make_float4(0.f, 0.f, 0.f, 0.f);
#pragma unroll
        for (int ks = 0; ks < NSP; ks++) {
            float4 p = ((const float4*)g_qWa_part[ks])[b * 256 + tid];
            r.x += p.x; r.y += p.y; r.z += p.z; r.w += p.w;
        }
        qs[tid] = r;
    }
    __syncthreads();
    int w = tid >> 5, l = tid & 31;
    int bs = b * NS + s0 + w;
    const float4* uk = (const float4*)(g_Uk) + (size_t)bs * (NH / 4);
    const float4* v = (const float4*)Va;
    float sum = 0.f;
#pragma unroll
    for (int i = 0; i < 8; i++) {
        int idx = l + 32 * i;
        float4 u = uk[idx], qq = qs[idx], vv = v[idx];
        sum += vv.x * tanh_fast(u.x + qq.x);
        sum += vv.y * tanh_fast(u.y + qq.y);
        sum += vv.z * tanh_fast(u.z + qq.z);
        sum += vv.w * tanh_fast(u.w + qq.w);
    }
#pragma unroll
    for (int o = 16; o; o >>= 1) sum += __shfl_xor_sync(0xffffffffu, sum, o);
    if (!l) g_scores[bs] = sum;
}

// ---------------------------------------------------------------------------
// Fused softmax + ctx + x-build + attn-out. grid (4 quarters, 64 b), 256 thr.
__global__ __launch_bounds__(256) void k_smctx(const unsigned char* __restrict__ mask,
                                               const float* __restrict__ enc,
                                               const float* __restrict__ emb,
                                               const int* __restrict__ target,
                                               const int* __restrict__ sos,
                                               float* __restrict__ out, int t) {
    int q = blockIdx.x, b = blockIdx.y;
    int tid = threadIdx.x;
    int lane = tid & 31, wid = tid >> 5;
    __shared__ float red[8];
    __shared__ float ws[NS];
    __shared__ float4 part[4][64];

    // --- softmax ---
    float v = g_scores[b * NS + tid];
    if (mask[b * NS + tid]) v = -1e30f;
    float m = v;
#pragma unroll
    for (int o = 16; o; o >>= 1) m = fmaxf(m, __shfl_xor_sync(0xffffffffu, m, o));
    if (!lane) red[wid] = m;
    __syncthreads();
    float bm = red[0];
#pragma unroll
    for (int i = 1; i < 8; i++) bm = fmaxf(bm, red[i]);
    float e = __expf(v - bm);
    float sum = e;
#pragma unroll
    for (int o = 16; o; o >>= 1) sum += __shfl_xor_sync(0xffffffffu, sum, o);
    __syncthreads();
    if (!lane) red[wid] = sum;
    __syncthreads();
    float bsum = 0.f;
#pragma unroll
    for (int i = 0; i < 8; i++) bsum += red[i];
    float w = e / bsum;
    ws[tid] = w;
    if (q == 0) out[OUT_ATTN + b * NT * NS + t * NS + tid] = w;

    // --- emb part of x : 128 floats per quarter ---
    if (tid < 128) {
        int tok = (t == 0) ? sos[0] : target[b * NT + t - 1];
        int j = q * 128 + tid;
        g_x[b * NXK + j] = rna_tf32(emb[tok * NE + j]);
    }
    __syncthreads();

    // --- ctx quarter: 64 float4 cols x 4 s-groups ---
    int c4 = q * 64 + (tid & 63);
    int sg = tid >> 6;
    const float4* e4 = (const float4*)(enc) + (size_t)b * NS * 256 + c4;
    float4 acc = make_float4(0.f, 0.f, 0.f, 0.f);
#pragma unroll 4
    for (int s = sg * 64; s < sg * 64 + 64; s++) {
        float4 ev = e4[(size_t)s * 256];
        float wv = ws[s];
        acc.x += wv * ev.x; acc.y += wv * ev.y;
        acc.z += wv * ev.z; acc.w += wv * ev.w;
    }
    part[sg][tid & 63] = acc;
    __syncthreads();
    if (tid < 64) {
        float4 a0 = part[0][tid], a1 = part[1][tid],
               a2 = part[2][tid], a3 = part[3][tid];
        float4 r = make_float4(a0.x + a1.x + a2.x + a3.x,
                               a0.y + a1.y + a2.y + a3.y,
                               a0.z + a1.z + a2.z + a3.z,
                               a0.w + a1.w + a2.w + a3.w);
        float* xp = g_x + b * NXK + NE + q * 256 + tid * 4;
        xp[0] = rna_tf32(r.x); xp[1] = rna_tf32(r.y);
        xp[2] = rna_tf32(r.z); xp[3] = rna_tf32(r.w);
    }
}

// ---------------------------------------------------------------------------
// LSTM pointwise: sums NSP gate partials + biases, writes c/hcat/hcat32.
__global__ __launch_bounds__(256) void k_cell(const float* __restrict__ bihf,
                                              const float* __restrict__ bhhf,
                                              const float* __restrict__ bihb,
                                              const float* __restrict__ bhhb) {
    int idx = blockIdx.x * 256 + threadIdx.x;    // [2][64][512]
    int d = idx >> 15;
    int r = idx & 32767;
    int b = r >> 9;
    int j = r & 511;
    const float* bih = d ? bihb : bihf;
    const float* bhh = d ? bhhb : bhhf;
    float gv[4];
#pragma unroll
    for (int g4 = 0; g4 < 4; g4++) {
        int gi = g4 * 512 + j;
        float s = bih[gi] + bhh[gi];
#pragma unroll
        for (int ks = 0; ks < NSP; ks++)
            s += g_gates_part[ks][d][b * NG + gi];
        gv[g4] = s;
    }
    float c = g_c[idx];
    float c2 = sigmoid_acc(gv[1]) * c + sigmoid_acc(gv[0]) * tanhf(gv[2]);
    g_c[idx] = c2;
    float h = sigmoid_acc(gv[3]) * tanhf(c2);
    g_hcat[b * NH + d * 512 + j] = h;
    g_hcat32[b * NH + d * 512 + j] = rna_tf32(h);
}

// ---------------------------------------------------------------------------
__global__ __launch_bounds__(256) void k_final(float* __restrict__ out) {
    int idx = blockIdx.x * 256 + threadIdx.x;   // [2][64][512]
    int d = idx >> 15, b = (idx >> 9) & 63, j = idx & 511;
    out[OUT_H + idx] = g_hcat[b * NH + d * 512 + j];
    out[OUT_C + idx] = g_c[idx];
}

// ---------------------------------------------------------------------------
extern "C" void kernel_launch(void* const* d_in, const int* in_sizes, int n_in,
                              void* d_out, int out_size) {
    (void)in_sizes; (void)n_in; (void)out_size;
    const float* enc   = (const float*)d_in[0];
    const float* h0    = (const float*)d_in[1];
    const float* c0    = (const float*)d_in[2];
    const int* target  = (const int*)d_in[3];
    const unsigned char* mask = (const unsigned char*)d_in[4];
    const int* sos     = (const int*)d_in[5];
    const float* emb   = (const float*)d_in[6];
    const float* Wa    = (const float*)d_in[7];
    const float* Ua    = (const float*)d_in[8];
    const float* Va    = (const float*)d_in[9];
    const float* outW  = (const float*)d_in[10];
    const float* outb  = (const float*)d_in[11];
    const float* Wihf  = (const float*)d_in[12];
    const float* Whhf  = (const float*)d_in[13];
    const float* bihf  = (const float*)d_in[14];
    const float* bhhf  = (const float*)d_in[15];
    const float* Wihb  = (const float*)d_in[16];
    const float* Whhb  = (const float*)d_in[17];
    const float* bihb  = (const float*)d_in[18];
    const float* bhhb  = (const float*)d_in[19];
    float* out = (float*)d_out;

    k_init<<<256, 256>>>(h0, c0);
    k_round_all<<<(int)((RN_TOT + 255) / 256), 256>>>(outW, Wa, Ua, Wihf, Wihb,
                                                      Whhf, Whhb, enc);
    k_mma_uk<<<dim3(16, 1, 256), 128>>>();
    k_qwa_step<<<128, 128>>>();

    for (int t = 0; t < NT; t++) {
        k_sclog<<<2205, 256>>>(Va, out, outb, t);   // scores(t) + logits(t-1)
        k_smctx<<<dim3(4, 64), 256>>>(mask, enc, emb, target, sos, out, t);
        k_mma_lstm<<<512, 128>>>();
        k_cell<<<256, 256>>>(bihf, bhhf, bihb, bhhb);
        if (t + 1 < NT) k_qwa_step<<<128, 128>>>(); // qWa for t+1
    }
    k_logits<<<157, 128>>>(out, outb, NT - 1);
    k_final<<<256, 256>>>(out);
}